// round 14
// baseline (speedup 1.0000x reference)
#include <cuda_runtime.h>
#include <math.h>
#include <stdint.h>

// Problem dims
#define XD     2048
#define INDIM  512
#define OUTDIM 256
#define BATCH  64
#define TSTEPS 128
#define BT     (BATCH*TSTEPS)   // 8192
#define KH     (2*XD)           // 4096
#define NCTA   128              // persistent grid (<=148 SMs, all resident)
#define NPHASE (TSTEPS*4)       // 512
#define NCHUNK (NPHASE*8)       // 4096 global B chunks

// int8 digit chunk layout: chunk = 64 k-cols, rows padded to 80 B
// (5x16 B: ldmatrix-aligned, conflict-free: bank stride 20 words).
// A chunk: 64 rows, planes [D1][D2]; B chunk: 128 rows, planes [E1][E2].
#define ROWB8 80
#define APL   (64*ROWB8)        // 5120  A plane
#define ACB8  (2*APL)           // 10240 A chunk
#define BPL   (128*ROWB8)       // 10240 B plane
#define BCB8  (2*BPL)           // 20480 B chunk

// Scratch (static __device__ per allocation rules)
__device__ float g_H0f[BT*XD];                      // 64 MB fp32 h0, all t
__device__ float g_H4f[BT*XD];                      // 64 MB fp32 h4, all t
__device__ float g_h1f[BATCH*XD];
__device__ float g_h2f[BATCH*XD];
__device__ float g_h3f[BATCH*XD];
__device__ float g_part[8*BATCH*XD];                // split-K fp32 partials
__device__ float g_np_li[2][NCTA];                  // li norm partials (t parity)
__device__ float g_np_bp[2][NCTA];                  // bp norm partials
__device__ unsigned g_cnt;
__device__ unsigned g_sense;
__device__ __align__(16) unsigned char g_Wq[4*16*8*8*BCB8];  // 84 MB int8 digits
__device__ float g_sb[4][8][XD];                    // weight scales (l, kb, n)

// ---------------------------------------------------------------------------
// helpers
// ---------------------------------------------------------------------------
__device__ __forceinline__ uint32_t s2u(const void* p) {
    uint32_t a;
    asm("{ .reg .u64 t; cvta.to.shared.u64 t, %1; cvt.u32.u64 %0, t; }"
        : "=r"(a) : "l"(p));
    return a;
}
__device__ __forceinline__ void mbar_init(uint32_t a, uint32_t c) {
    asm volatile("mbarrier.init.shared.b64 [%0], %1;" :: "r"(a), "r"(c) : "memory");
}
__device__ __forceinline__ void mbar_expect(uint32_t a, uint32_t bytes) {
    asm volatile("mbarrier.arrive.expect_tx.shared.b64 _, [%0], %1;"
                 :: "r"(a), "r"(bytes) : "memory");
}
__device__ __forceinline__ void mbar_wait(uint32_t a, uint32_t parity) {
    asm volatile(
        "{\n\t.reg .pred P1;\n\t"
        "W_%=:\n\t"
        "mbarrier.try_wait.parity.acquire.cta.shared::cta.b64 P1, [%0], %1, 0x989680;\n\t"
        "@P1 bra.uni D_%=;\n\t"
        "bra.uni W_%=;\n\t"
        "D_%=:\n\t}"
        :: "r"(a), "r"(parity) : "memory");
}
__device__ __forceinline__ void bulk_g2s(uint32_t dst, const void* src,
                                         uint32_t bytes, uint32_t mbar) {
    asm volatile(
        "cp.async.bulk.shared::cluster.global.mbarrier::complete_tx::bytes "
        "[%0], [%1], %2, [%3];"
        :: "r"(dst), "l"(src), "r"(bytes), "r"(mbar) : "memory");
}
__device__ __forceinline__ void ldsm4(uint32_t* r, uint32_t a) {
    asm volatile("ldmatrix.sync.aligned.m8n8.x4.shared.b16 {%0,%1,%2,%3}, [%4];"
        : "=r"(r[0]), "=r"(r[1]), "=r"(r[2]), "=r"(r[3]) : "r"(a));
}
#define PROXY_FENCE()  asm volatile("fence.proxy.async.shared::cta;" ::: "memory")

// int8 m16n8k32 tensor MMA, s32 accumulate
#define IMMA(c, a, b) \
    asm volatile("mma.sync.aligned.m16n8k32.row.col.s32.s8.s8.s32 " \
        "{%0,%1,%2,%3}, {%4,%5,%6,%7}, {%8,%9}, {%0,%1,%2,%3};" \
        : "+r"((c)[0]), "+r"((c)[1]), "+r"((c)[2]), "+r"((c)[3]) \
        : "r"((a)[0]), "r"((a)[1]), "r"((a)[2]), "r"((a)[3]), \
          "r"((b)[0]), "r"((b)[1]))

__device__ __forceinline__ float act_f(float h, int id) {
    switch (id) {
    case 0: return h > 0.f ? h : 0.f;
    case 1: return 1.f / (1.f + expf(-h));
    case 2: return tanhf(h);
    case 3: return h >= 0.f ? h : 0.1f * h;
    default: {
        const float sc = 1.0507009873554805f;
        const float al = 1.6732632423543772f;
        return h > 0.f ? sc * h : sc * al * expm1f(h);
    }
    }
}

// Sense-reversal grid barrier (all NCTA CTAs co-resident).
__device__ __forceinline__ void gbar(unsigned& ls) {
    __syncthreads();
    if (threadIdx.x == 0) {
        ls++;
        __threadfence();
        unsigned prev = atomicAdd(&g_cnt, 1u);
        if (prev == ls * NCTA - 1u) {
            atomicExch(&g_sense, ls);
        } else {
            while (*(volatile unsigned*)&g_sense < ls) { }
        }
        __threadfence();
    }
    __syncthreads();
}

// ---------------------------------------------------------------------------
// Reduce split-K partials + bias + activation. Slices 4-7 (A2 operand)
// optionally scaled per-row by fused l2-norm of the recurrent carry.
// ---------------------------------------------------------------------------
__device__ __forceinline__ void reduce_phase(
    const float* __restrict__ bias,
    const int*   __restrict__ ids,
    float* __restrict__ dst32, long ldc,
    const float* __restrict__ npr, int zr,
    float* __restrict__ npw, int cta)
{
    const int idx = cta * 1024 + threadIdx.x * 4;
    const int m   = idx >> 11;
    const int n   = idx & (XD - 1);

    float4 lo4 = *(const float4*)&g_part[idx];
    #pragma unroll
    for (int kb = 1; kb < 4; kb++) {
        const float4 p = *(const float4*)&g_part[(size_t)kb * BATCH * XD + idx];
        lo4.x += p.x; lo4.y += p.y; lo4.z += p.z; lo4.w += p.w;
    }
    float4 hi4 = *(const float4*)&g_part[(size_t)4 * BATCH * XD + idx];
    #pragma unroll
    for (int kb = 5; kb < 8; kb++) {
        const float4 p = *(const float4*)&g_part[(size_t)kb * BATCH * XD + idx];
        hi4.x += p.x; hi4.y += p.y; hi4.z += p.z; hi4.w += p.w;
    }
    float sm = 1.f;
    if (npr) {
        if (zr) sm = 0.f;
        else {
            const float ss = npr[2*m] + npr[2*m + 1];
            sm = 1.f / fmaxf(sqrtf(ss), 1e-12f);
        }
    }
    const float4 b = *(const float4*)&bias[n];
    float4 o;
    o.x = act_f(fmaf(sm, hi4.x, lo4.x) + b.x, ids[n+0]);
    o.y = act_f(fmaf(sm, hi4.y, lo4.y) + b.y, ids[n+1]);
    o.z = act_f(fmaf(sm, hi4.z, lo4.z) + b.z, ids[n+2]);
    o.w = act_f(fmaf(sm, hi4.w, lo4.w) + b.w, ids[n+3]);

    *(float4*)&dst32[(size_t)m * ldc + n] = o;

    if (npw) {
        float q = fmaf(o.x, o.x, fmaf(o.y, o.y, fmaf(o.z, o.z, o.w * o.w)));
        #pragma unroll
        for (int off = 16; off; off >>= 1)
            q += __shfl_down_sync(0xffffffffu, q, off);
        __shared__ float smq[8];
        if ((threadIdx.x & 31) == 0) smq[threadIdx.x >> 5] = q;
        __syncthreads();
        if (threadIdx.x == 0) {
            float tot = 0.f;
            #pragma unroll
            for (int i = 0; i < 8; i++) tot += smq[i];
            npw[cta] = tot;
        }
        __syncthreads();
    }
}

// ---------------------------------------------------------------------------
// Weight prep: fp32 W_h -> int8 digit planes + per-(l,kb,n) scale.
// One warp per (l, kb, n): 512 weights, slice-local max, 2 digits each.
// ---------------------------------------------------------------------------
__global__ void prep_w(const float* __restrict__ W)
{
    const int w    = blockIdx.x * 8 + (threadIdx.x >> 5);   // 65536 warps
    const int lane = threadIdx.x & 31;
    const int n  = w & 2047;
    const int kb = (w >> 11) & 7;
    const int l  = w >> 14;

    const float* src = W + (((size_t)l * XD + n) * KH + kb * 512 + lane * 16);
    float4 v[4];
    float mx = 0.f;
    #pragma unroll
    for (int i = 0; i < 4; i++) {
        v[i] = *(const float4*)(src + i * 4);
        mx = fmaxf(mx, fmaxf(fmaxf(fabsf(v[i].x), fabsf(v[i].y)),
                             fmaxf(fabsf(v[i].z), fabsf(v[i].w))));
    }
    #pragma unroll
    for (int off = 16; off; off >>= 1)
        mx = fmaxf(mx, __shfl_xor_sync(0xffffffffu, mx, off));

    const float s   = mx * (1.f / 127.f);
    const float inv = (mx > 0.f) ? 127.f / mx : 0.f;
    if (lane == 0) g_sb[l][kb][n] = s;

    const int nt = n >> 7, rw = n & 127;
    const int c = lane >> 2, klocal = (lane & 3) * 16;
    unsigned char* dst = g_Wq
        + ((size_t)((l * 16 + nt) * 8 + kb) * 8 + c) * BCB8
        + (size_t)rw * ROWB8 + klocal;

    uint32_t w1[4], w2[4];
    #pragma unroll
    for (int i = 0; i < 4; i++) {
        const float e[4] = { v[i].x, v[i].y, v[i].z, v[i].w };
        uint32_t p1 = 0, p2 = 0;
        #pragma unroll
        for (int j = 0; j < 4; j++) {
            const float q  = e[j] * inv;
            const float d1 = rintf(q);
            const float d2 = rintf((q - d1) * 128.f);
            p1 |= ((uint32_t)((int)d1 & 255)) << (8 * j);
            p2 |= ((uint32_t)((int)d2 & 255)) << (8 * j);
        }
        w1[i] = p1; w2[i] = p2;
    }
    *(uint4*)dst         = make_uint4(w1[0], w1[1], w1[2], w1[3]);
    *(uint4*)(dst + BPL) = make_uint4(w2[0], w2[1], w2[2], w2[3]);
}

// ---------------------------------------------------------------------------
// Persistent kernel. SMEM: [A digits 8 chunks][B stage0][B stage1].
// Per phase: convert fp32 A slice -> int8 digits (slice-local row scales),
// then 8 chunks of 3-product IMMA; epilogue dequants to fp32 partials.
// ---------------------------------------------------------------------------
__global__ void __launch_bounds__(256, 1)
rnn_persistent(const float* __restrict__ b_h,
               const int*   __restrict__ act_ids)
{
    extern __shared__ char dsm[];
    __shared__ __align__(8) unsigned long long s_mbB[2];
    __shared__ float sSA[64];     // A row scales (slice-local)
    __shared__ float sSB[128];    // B row scales for this CTA's 128 n-cols

    const int tid = threadIdx.x, wid = tid >> 5, lane = tid & 31;
    const int cta = blockIdx.x, nt = cta & 15, kb = cta >> 4;

    const uint32_t raw = s2u(dsm);
    const uint32_t A0u = (raw + 127) & ~127u;
    const uint32_t B0u = A0u + 8 * ACB8;
    char* RA = dsm + (A0u - raw);
    const uint32_t mbB[2] = { s2u(&s_mbB[0]), s2u(&s_mbB[1]) };

    if (tid == 0) {
        mbar_init(mbB[0], 1); mbar_init(mbB[1], 1);
        PROXY_FENCE();
    }
    __syncthreads();

    auto issueB = [&](long cg) {
        if (cg >= NCHUNK) return;
        const int s = (int)(cg & 1);
        const int p = (int)((cg >> 3) & 3);
        const int c = (int)(cg & 7);
        const unsigned char* src =
            g_Wq + ((size_t)((p * 16 + nt) * 8 + kb) * 8 + c) * BCB8;
        mbar_expect(mbB[s], (uint32_t)BCB8);
        bulk_g2s(B0u + s * BCB8, src, (uint32_t)BCB8, mbB[s]);
    };
    if (tid == 0) { issueB(0); issueB(1); }

    // fragment geometry (identical mapping to bf16, byte-for-byte)
    const int g  = lane >> 2, i4 = lane & 3;
    const int wm = (wid >> 2) * 32;
    const int wn = (wid & 3) * 32;
    const int l15 = lane & 15, lk = lane >> 4;
    const uint32_t aoff0 = (uint32_t)((wm + l15) * ROWB8 + lk * 16);
    const uint32_t aoff1 = (uint32_t)((wm + 16 + l15) * ROWB8 + lk * 16);
    const int lr = lane & 7, ls8 = (lane >> 3) & 1;
    const uint32_t boff0 = (uint32_t)((wn + lk * 8 + lr) * ROWB8 + ls8 * 16);
    const uint32_t boff1 = (uint32_t)((wn + 16 + lk * 8 + lr) * ROWB8 + ls8 * 16);

    // A-converter thread mapping: (row m, quarter q4) -> 128 cols
    const int cm = tid >> 2, cq = tid & 3;

    int phb[2] = { 0, 0 };
    unsigned ls = 0;

    for (int pidx = 0; pidx < NPHASE; pidx++) {
        const int t = pidx >> 2, phn = pidx & 3;

        // phase fp32 sources / sinks
        const float *A1f, *A2f; long astr;
        const float* bias; const int* ids;
        float* dst32; long ldc = XD;
        const float* npr = nullptr; float* npw = nullptr; int zr = 0;
        if (phn == 0) {
            A1f = g_H0f + (size_t)t * XD;
            A2f = g_H4f + (size_t)(t ? t - 1 : 0) * XD;
            astr = (long)TSTEPS * XD;
            npr = g_np_bp[(t + 1) & 1]; zr = (t == 0);
            bias = b_h;        ids = act_ids + XD;     dst32 = g_h1f;
        } else if (phn == 1) {
            A1f = g_h1f; A2f = g_h2f; astr = XD;
            npr = g_np_li[(t + 1) & 1]; zr = (t == 0);
            npw = g_np_li[t & 1];
            bias = b_h + XD;   ids = act_ids + 2*XD;   dst32 = g_h2f;
        } else if (phn == 2) {
            A1f = g_h2f; A2f = g_h1f; astr = XD;
            bias = b_h + 2*XD; ids = act_ids + 3*XD;   dst32 = g_h3f;
        } else {
            A1f = g_h3f; A2f = g_h2f; astr = XD;
            npw = g_np_bp[t & 1];
            bias = b_h + 3*XD; ids = act_ids + 4*XD;
            dst32 = g_H4f + (size_t)t * XD; ldc = (long)TSTEPS * XD;
        }

        // ---- Convert this CTA's fp32 A slice (64x512) to int8 digits ----
        {
            const float* src = (kb < 4) ? A1f + kb * 512
                                        : A2f + (kb - 4) * 512;
            const float* rp = src + (size_t)cm * astr + cq * 128;
            float4 u[32];
            float mx = 0.f;
            #pragma unroll
            for (int i = 0; i < 32; i++) {
                u[i] = *(const float4*)(rp + i * 4);
                mx = fmaxf(mx, fmaxf(fmaxf(fabsf(u[i].x), fabsf(u[i].y)),
                                     fmaxf(fabsf(u[i].z), fabsf(u[i].w))));
            }
            mx = fmaxf(mx, __shfl_xor_sync(0xffffffffu, mx, 1));
            mx = fmaxf(mx, __shfl_xor_sync(0xffffffffu, mx, 2));
            const float s   = mx * (1.f / 127.f);
            const float inv = (mx > 0.f) ? 127.f / mx : 0.f;
            if (cq == 0) sSA[cm] = s;
            #pragma unroll
            for (int i = 0; i < 32; i++) {
                const int col = cq * 128 + i * 4;
                const int ch = col >> 6, klocal = col & 63;
                const float e[4] = { u[i].x, u[i].y, u[i].z, u[i].w };
                uint32_t p1 = 0, p2 = 0;
                #pragma unroll
                for (int j = 0; j < 4; j++) {
                    const float q  = e[j] * inv;
                    const float d1 = rintf(q);
                    const float d2 = rintf((q - d1) * 128.f);
                    p1 |= ((uint32_t)((int)d1 & 255)) << (8 * j);
                    p2 |= ((uint32_t)((int)d2 & 255)) << (8 * j);
                }
                char* a = RA + ch * ACB8 + cm * ROWB8 + klocal;
                *(uint32_t*)a         = p1;
                *(uint32_t*)(a + APL) = p2;
            }
            if (tid < 128) sSB[tid] = g_sb[phn][kb][nt * 128 + tid];
        }
        __syncthreads();

        int accA[2][4][4], accB[2][4][4];   // P1 and P23 accumulators
        #pragma unroll
        for (int mt = 0; mt < 2; mt++)
            #pragma unroll
            for (int n4 = 0; n4 < 4; n4++)
                #pragma unroll
                for (int j = 0; j < 4; j++) { accA[mt][n4][j] = 0; accB[mt][n4][j] = 0; }

        const long cgb = (long)pidx * 8;
        #pragma unroll 1
        for (int c = 0; c < 8; c++) {
            const int s = c & 1;
            mbar_wait(mbB[s], (uint32_t)phb[s]); phb[s] ^= 1;

            const uint32_t bA = A0u + c * ACB8;
            const uint32_t bB = B0u + s * BCB8;

            #pragma unroll
            for (int j = 0; j < 2; j++) {      // two k32 steps per 64-k chunk
                const uint32_t kof = j * 32;
                uint32_t a1[2][4], a2[2][4], b1[2][4], b2[2][4];
                ldsm4(a1[0], bA + aoff0 + kof);
                ldsm4(a1[1], bA + aoff1 + kof);
                ldsm4(a2[0], bA + APL + aoff0 + kof);
                ldsm4(a2[1], bA + APL + aoff1 + kof);
                ldsm4(b1[0], bB + boff0 + kof);
                ldsm4(b1[1], bB + boff1 + kof);
                ldsm4(b2[0], bB + BPL + boff0 + kof);
                ldsm4(b2[1], bB + BPL + boff1 + kof);
                #pragma unroll
                for (int mt = 0; mt < 2; mt++)
                    #pragma unroll
                    for (int P = 0; P < 2; P++) {
                        IMMA(accA[mt][2*P],   a1[mt], b1[P] + 0);
                        IMMA(accB[mt][2*P],   a1[mt], b2[P] + 0);
                        IMMA(accB[mt][2*P],   a2[mt], b1[P] + 0);
                        IMMA(accA[mt][2*P+1], a1[mt], b1[P] + 2);
                        IMMA(accB[mt][2*P+1], a1[mt], b2[P] + 2);
                        IMMA(accB[mt][2*P+1], a2[mt], b1[P] + 2);
                    }
            }
            __syncthreads();
            if (tid == 0) issueB(cgb + c + 2);   // crosses into next phase
        }

        // epilogue: dequant + write split-K partials
        {
            float* P = g_part + (size_t)kb * BATCH * XD;
            #pragma unroll
            for (int mt = 0; mt < 2; mt++) {
                const int m0 = wm + mt * 16 + g;
                const float sa0 = sSA[m0], sa1 = sSA[m0 + 8];
                #pragma unroll
                for (int n4 = 0; n4 < 4; n4++) {
                    const int nl = wn + n4 * 8 + i4 * 2;
                    const float sb0 = sSB[nl], sb1 = sSB[nl + 1];
                    const int* pa = accA[mt][n4];
                    const int* pb = accB[mt][n4];
                    const int col = nt * 128 + nl;
                    float2 r0, r1;
                    r0.x = sa0 * sb0 * fmaf((float)pb[0], 0.0078125f, (float)pa[0]);
                    r0.y = sa0 * sb1 * fmaf((float)pb[1], 0.0078125f, (float)pa[1]);
                    r1.x = sa1 * sb0 * fmaf((float)pb[2], 0.0078125f, (float)pa[2]);
                    r1.y = sa1 * sb1 * fmaf((float)pb[3], 0.0078125f, (float)pa[3]);
                    *(float2*)&P[(size_t)m0 * XD + col]       = r0;
                    *(float2*)&P[(size_t)(m0 + 8) * XD + col] = r1;
                }
            }
        }

        gbar(ls);
        reduce_phase(bias, ids, dst32, ldc, npr, zr, npw, cta);
        gbar(ls);
    }
}

// ---------------------------------------------------------------------------
// Parallel fp32 SIMT GEMM with fused bias+activation (edge GEMMs).
// ---------------------------------------------------------------------------
__global__ void __launch_bounds__(256, 1)
gemm_big(const float* __restrict__ A, int lda,
         const float* __restrict__ W, int K,
         const float* __restrict__ bias,
         const int*   __restrict__ ids,
         float* __restrict__ C, int ldc)
{
    __shared__ float As[32][64];
    __shared__ float Ws[32][128];

    const int t  = threadIdx.x;
    const int n0 = blockIdx.x * 128;
    const int m0 = blockIdx.y * 64;

    const int am  = t & 63;
    const int akq = t >> 6;
    const int wn  = t & 127;
    const int wkq = t >> 7;

    const float* Aptr = A + (size_t)(m0 + am) * lda + akq * 8;
    const float* Wptr = W + (size_t)(n0 + wn) * K + wkq * 16;

    float4 pa0 = *(const float4*)(Aptr + 0);
    float4 pa1 = *(const float4*)(Aptr + 4);
    float4 pw0 = *(const float4*)(Wptr + 0);
    float4 pw1 = *(const float4*)(Wptr + 4);
    float4 pw2 = *(const float4*)(Wptr + 8);
    float4 pw3 = *(const float4*)(Wptr + 12);

    const int tx = t & 31;
    const int ty = t >> 5;

    float c[8][4];
    #pragma unroll
    for (int i = 0; i < 8; i++)
        #pragma unroll
        for (int j = 0; j < 4; j++) c[i][j] = 0.f;

    const int NC = K / 32;
    #pragma unroll 1
    for (int ch = 0; ch < NC; ch++) {
        __syncthreads();
        As[akq*8+0][am] = pa0.x; As[akq*8+1][am] = pa0.y;
        As[akq*8+2][am] = pa0.z; As[akq*8+3][am] = pa0.w;
        As[akq*8+4][am] = pa1.x; As[akq*8+5][am] = pa1.y;
        As[akq*8+6][am] = pa1.z; As[akq*8+7][am] = pa1.w;
        Ws[wkq*16+ 0][wn] = pw0.x; Ws[wkq*16+ 1][wn] = pw0.y;
        Ws[wkq*16+ 2][wn] = pw0.z; Ws[wkq*16+ 3][wn] = pw0.w;
        Ws[wkq*16+ 4][wn] = pw1.x; Ws[wkq*16+ 5][wn] = pw1.y;
        Ws[wkq*16+ 6][wn] = pw1.z; Ws[wkq*16+ 7][wn] = pw1.w;
        Ws[wkq*16+ 8][wn] = pw2.x; Ws[wkq*16+ 9][wn] = pw2.y;
        Ws[wkq*16+10][wn] = pw2.z; Ws[wkq*16+11][wn] = pw2.w;
        Ws[wkq*16+12][wn] = pw3.x; Ws[wkq*16+13][wn] = pw3.y;
        Ws[wkq*16+14][wn] = pw3.z; Ws[wkq*16+15][wn] = pw3.w;
        __syncthreads();

        if (ch + 1 < NC) {
            Aptr += 32; Wptr += 32;
            pa0 = *(const float4*)(Aptr + 0);
            pa1 = *(const float4*)(Aptr + 4);
            pw0 = *(const float4*)(Wptr + 0);
            pw1 = *(const float4*)(Wptr + 4);
            pw2 = *(const float4*)(Wptr + 8);
            pw3 = *(const float4*)(Wptr + 12);
        }

        #pragma unroll
        for (int kk = 0; kk < 32; kk++) {
            const float4 a0 = *(const float4*)&As[kk][ty*8];
            const float4 a1 = *(const float4*)&As[kk][ty*8+4];
            const float4 w  = *(const float4*)&Ws[kk][tx*4];
            const float av[8] = {a0.x,a0.y,a0.z,a0.w,a1.x,a1.y,a1.z,a1.w};
            const float wv[4] = {w.x,w.y,w.z,w.w};
            #pragma unroll
            for (int i = 0; i < 8; i++)
                #pragma unroll
                for (int j = 0; j < 4; j++)
                    c[i][j] = fmaf(av[i], wv[j], c[i][j]);
        }
    }

    #pragma unroll
    for (int i = 0; i < 8; i++) {
        const int m = m0 + ty * 8 + i;
        const int n = n0 + tx * 4;
        float4 o;
        o.x = act_f(c[i][0] + bias[n+0], ids[n+0]);
        o.y = act_f(c[i][1] + bias[n+1], ids[n+1]);
        o.z = act_f(c[i][2] + bias[n+2], ids[n+2]);
        o.w = act_f(c[i][3] + bias[n+3], ids[n+3]);
        *(float4*)&C[(size_t)m * ldc + n] = o;
    }
}

// Zero barrier state + carry buffers consumed (scaled by 0) at t=0.
__global__ void init_state()
{
    const int i = blockIdx.x * blockDim.x + threadIdx.x;   // 73728 threads
    if (i == 0) { g_cnt = 0u; g_sense = 0u; }
    const float4 z = make_float4(0.f, 0.f, 0.f, 0.f);
    if (i < 32768) {
        *(float4*)&g_h2f[i * 4] = z;
        const int m = i >> 9, c4 = (i & 511) * 4;
        *(float4*)&g_H4f[((size_t)m * TSTEPS) * XD + c4] = z;   // t=0 slice
    }
}

// ---------------------------------------------------------------------------
extern "C" void kernel_launch(void* const* d_in, const int* in_sizes, int n_in,
                              void* d_out, int out_size)
{
    const float* x        = (const float*)d_in[0];  // [64,128,512]
    const float* W_in     = (const float*)d_in[1];  // [2048,512]
    const float* b_in     = (const float*)d_in[2];  // [2048]
    const float* W_h      = (const float*)d_in[3];  // [4,2048,4096]
    const float* b_h      = (const float*)d_in[4];  // [4,2048]
    const float* W_out    = (const float*)d_in[5];  // [256,2048]
    const float* b_out    = (const float*)d_in[6];  // [256]
    const int*   act_ids  = (const int*)d_in[7];    // [5,2048]
    const int*   oact_ids = (const int*)d_in[8];    // [256]
    float*       out      = (float*)d_out;          // [64,128,256]

    float *H0f, *H4f;
    cudaGetSymbolAddress((void**)&H0f, g_H0f);
    cudaGetSymbolAddress((void**)&H4f, g_H4f);

    const int smem = 8 * ACB8 + 2 * BCB8 + 128;     // 123,008
    cudaFuncSetAttribute(rnn_persistent,
                         cudaFuncAttributeMaxDynamicSharedMemorySize, smem);

    init_state<<<288, 256>>>();
    prep_w<<<8192, 256>>>(W_h);

    // H0 = act0(x @ W_in^T + b_in), fp32, all (b,t)
    gemm_big<<<dim3(XD/128, BT/64), 256>>>(x, INDIM, W_in, INDIM,
                                           b_in, act_ids, H0f, XD);

    // Entire recurrent loop: persistent int8-IMMA kernel.
    rnn_persistent<<<NCTA, 256, smem>>>(b_h, act_ids);

    // y = act_out(H4 @ W_out^T + b_out)
    gemm_big<<<dim3(OUTDIM/128, BT/64), 256>>>(H4f, XD, W_out, XD,
                                               b_out, oact_ids, out, OUTDIM);
}

// round 17
// speedup vs baseline: 2.3295x; 2.3295x over previous
#include <cuda_runtime.h>
#include <cuda_fp16.h>
#include <math.h>
#include <stdint.h>

// Problem dims
#define XD     2048
#define INDIM  512
#define OUTDIM 256
#define BATCH  64
#define TSTEPS 128
#define BT     (BATCH*TSTEPS)   // 8192
#define KH     (2*XD)           // 4096
#define NCTA   128              // persistent grid (<=148 SMs, all resident)
#define NPHASE (TSTEPS*4)       // 512
#define NCHUNK (NPHASE*8)       // 4096 global B chunks

// fp16 chunk-padded layout: chunk = 64 k-cols, rows padded to 72 fp16 (144 B)
// — conflict-free for LDSM. A chunk (64 rows): single plane, 9216 B.
// B chunk (128 rows): [hi 18432][lo 18432] = 36864 B.
#define ACBA  9216
#define BPL   18432
#define BCB   36864
#define ROWB  144

// Scratch (static __device__ per allocation rules)
__device__ float g_H4[BT*XD];                       // fp32 h4 (head GEMM input)
__device__ float g_part[8*BATCH*XD];                // split-K partials
__device__ float g_np_li[2][NCTA];                  // li norm partials (t parity)
__device__ float g_np_bp[2][NCTA];                  // bp norm partials
__device__ unsigned g_cnt;
__device__ unsigned g_sense;
__device__ __align__(16) unsigned char g_Wp[4*16*8*8*BCB];   // 151 MB fp16 hi/lo
__device__ __align__(16) unsigned char g_H0b[128*32*ACBA];   // h0 fp16, per t
__device__ __align__(16) unsigned char g_H4b[128*32*ACBA];   // h4 fp16, per t
__device__ __align__(16) unsigned char g_h1b[32*ACBA];
__device__ __align__(16) unsigned char g_h2b[32*ACBA];
__device__ __align__(16) unsigned char g_h3b[32*ACBA];
// Power-of-2 range scales (2^e multipliers), indexed [2*m + half]
__device__ float g_saH0[128*128];                   // per t
__device__ float g_saH4[128*128];                   // per t
__device__ float g_sa1[128];
__device__ float g_sa2[128];
__device__ float g_sa3[128];

// ---------------------------------------------------------------------------
// helpers
// ---------------------------------------------------------------------------
__device__ __forceinline__ uint32_t s2u(const void* p) {
    uint32_t a;
    asm("{ .reg .u64 t; cvta.to.shared.u64 t, %1; cvt.u32.u64 %0, t; }"
        : "=r"(a) : "l"(p));
    return a;
}

__device__ __forceinline__ uint32_t packh(float a, float b) {
    __half2 h = __float22half2_rn(make_float2(a, b));
    return *(uint32_t*)&h;
}
__device__ __forceinline__ void split2h(float a, float b, uint32_t& h, uint32_t& l) {
    __half2 hp = __float22half2_rn(make_float2(a, b));
    float2 hf = __half22float2(hp);
    __half2 lp = __float22half2_rn(make_float2(a - hf.x, b - hf.y));
    h = *(uint32_t*)&hp;
    l = *(uint32_t*)&lp;
}

__device__ __forceinline__ void mbar_init(uint32_t a, uint32_t c) {
    asm volatile("mbarrier.init.shared.b64 [%0], %1;" :: "r"(a), "r"(c) : "memory");
}
__device__ __forceinline__ void mbar_expect(uint32_t a, uint32_t bytes) {
    asm volatile("mbarrier.arrive.expect_tx.shared.b64 _, [%0], %1;"
                 :: "r"(a), "r"(bytes) : "memory");
}
__device__ __forceinline__ void mbar_wait(uint32_t a, uint32_t parity) {
    asm volatile(
        "{\n\t.reg .pred P1;\n\t"
        "W_%=:\n\t"
        "mbarrier.try_wait.parity.acquire.cta.shared::cta.b64 P1, [%0], %1, 0x989680;\n\t"
        "@P1 bra.uni D_%=;\n\t"
        "bra.uni W_%=;\n\t"
        "D_%=:\n\t}"
        :: "r"(a), "r"(parity) : "memory");
}
__device__ __forceinline__ void bulk_g2s(uint32_t dst, const void* src,
                                         uint32_t bytes, uint32_t mbar) {
    asm volatile(
        "cp.async.bulk.shared::cluster.global.mbarrier::complete_tx::bytes "
        "[%0], [%1], %2, [%3];"
        :: "r"(dst), "l"(src), "r"(bytes), "r"(mbar) : "memory");
}
__device__ __forceinline__ void ldsm4(uint32_t* r, uint32_t a) {
    asm volatile("ldmatrix.sync.aligned.m8n8.x4.shared.b16 {%0,%1,%2,%3}, [%4];"
        : "=r"(r[0]), "=r"(r[1]), "=r"(r[2]), "=r"(r[3]) : "r"(a));
}
#define PROXY_FENCE()  asm volatile("fence.proxy.async.shared::cta;" ::: "memory")

#define MMA(c, a, b) \
    asm volatile("mma.sync.aligned.m16n8k16.row.col.f32.f16.f16.f32 " \
        "{%0,%1,%2,%3}, {%4,%5,%6,%7}, {%8,%9}, {%0,%1,%2,%3};" \
        : "+f"((c)[0]), "+f"((c)[1]), "+f"((c)[2]), "+f"((c)[3]) \
        : "r"((a)[0]), "r"((a)[1]), "r"((a)[2]), "r"((a)[3]), \
          "r"((b)[0]), "r"((b)[1]))

__device__ __forceinline__ float act_f(float h, int id) {
    switch (id) {
    case 0: return h > 0.f ? h : 0.f;
    case 1: return 1.f / (1.f + expf(-h));
    case 2: return tanhf(h);
    case 3: return h >= 0.f ? h : 0.1f * h;
    default: {
        const float sc = 1.0507009873554805f;
        const float al = 1.6732632423543772f;
        return h > 0.f ? sc * h : sc * al * expm1f(h);
    }
    }
}

// Sense-reversal grid barrier (all NCTA CTAs co-resident).
__device__ __forceinline__ void gbar(unsigned& ls) {
    __syncthreads();
    if (threadIdx.x == 0) {
        ls++;
        __threadfence();
        unsigned prev = atomicAdd(&g_cnt, 1u);
        if (prev == ls * NCTA - 1u) {
            atomicExch(&g_sense, ls);
        } else {
            while (*(volatile unsigned*)&g_sense < ls) { }
        }
        __threadfence();
    }
    __syncthreads();
}

// ---------------------------------------------------------------------------
// Reduce split-K partials + bias + activation. kb>=4 partials optionally
// scaled per-row by the fused l2-norm of the recurrent carry (linearity).
// Writes fp16 chunk layout with per-half-row power-of-2 range scaling
// (exact; multiplier 2^e stored in saw[cta]).
// ---------------------------------------------------------------------------
__device__ __forceinline__ void reduce_phase(
    const float* __restrict__ bias,
    const int*   __restrict__ ids,
    float* __restrict__ dst32, long ldc,
    unsigned char* __restrict__ dstb,
    float* __restrict__ saw,
    const float* __restrict__ npr, int zr,
    float* __restrict__ npw, int cta)
{
    const int idx = cta * 1024 + threadIdx.x * 4;
    const int m   = idx >> 11;
    const int n   = idx & (XD - 1);

    float4 lo4 = *(const float4*)&g_part[idx];
    #pragma unroll
    for (int kb = 1; kb < 4; kb++) {
        const float4 p = *(const float4*)&g_part[(size_t)kb * BATCH * XD + idx];
        lo4.x += p.x; lo4.y += p.y; lo4.z += p.z; lo4.w += p.w;
    }
    float4 hi4 = *(const float4*)&g_part[(size_t)4 * BATCH * XD + idx];
    #pragma unroll
    for (int kb = 5; kb < 8; kb++) {
        const float4 p = *(const float4*)&g_part[(size_t)kb * BATCH * XD + idx];
        hi4.x += p.x; hi4.y += p.y; hi4.z += p.z; hi4.w += p.w;
    }
    float sm = 1.f;
    if (npr) {
        if (zr) sm = 0.f;
        else {
            const float ss = npr[2*m] + npr[2*m + 1];
            sm = 1.f / fmaxf(sqrtf(ss), 1e-12f);
        }
    }
    const float4 b = *(const float4*)&bias[n];
    float4 o;
    o.x = act_f(fmaf(sm, hi4.x, lo4.x) + b.x, ids[n+0]);
    o.y = act_f(fmaf(sm, hi4.y, lo4.y) + b.y, ids[n+1]);
    o.z = act_f(fmaf(sm, hi4.z, lo4.z) + b.z, ids[n+2]);
    o.w = act_f(fmaf(sm, hi4.w, lo4.w) + b.w, ids[n+3]);

    if (dst32) *(float4*)&dst32[(size_t)m * ldc + n] = o;

    // half-row max -> power-of-2 scale so fp16 never overflows (exact)
    float mxv = fmaxf(fmaxf(fabsf(o.x), fabsf(o.y)),
                      fmaxf(fabsf(o.z), fabsf(o.w)));
    #pragma unroll
    for (int off = 16; off; off >>= 1)
        mxv = fmaxf(mxv, __shfl_xor_sync(0xffffffffu, mxv, off));
    __shared__ float smx[8];
    if ((threadIdx.x & 31) == 0) smx[threadIdx.x >> 5] = mxv;
    __syncthreads();
    float mall = smx[0];
    #pragma unroll
    for (int i = 1; i < 8; i++) mall = fmaxf(mall, smx[i]);
    int e = 0;
    if (mall >= 16384.f) e = ilogbf(mall) - 13;   // scaled max < 2^14
    const float sdown = exp2f((float)(-e));
    if (threadIdx.x == 0) saw[cta] = exp2f((float)e);

    {
        const int g = n >> 6, col = n & 63;
        unsigned char* base = dstb + (size_t)g * ACBA + m * ROWB + col * 2;
        *(uint2*)base = make_uint2(packh(o.x * sdown, o.y * sdown),
                                   packh(o.z * sdown, o.w * sdown));
    }

    if (npw) {
        float q = fmaf(o.x, o.x, fmaf(o.y, o.y, fmaf(o.z, o.z, o.w * o.w)));
        #pragma unroll
        for (int off = 16; off; off >>= 1)
            q += __shfl_down_sync(0xffffffffu, q, off);
        __shared__ float smq[8];
        if ((threadIdx.x & 31) == 0) smq[threadIdx.x >> 5] = q;
        __syncthreads();
        if (threadIdx.x == 0) {
            float tot = 0.f;
            #pragma unroll
            for (int i = 0; i < 8; i++) tot += smq[i];
            npw[cta] = tot;
        }
        __syncthreads();
    }
}

// ---------------------------------------------------------------------------
// Weight preprocessing: fp32 W_h -> fp16 hi/lo chunk-padded blocks.
// ---------------------------------------------------------------------------
__global__ void prep_w(const float* __restrict__ W)
{
    const long idx = (long)blockIdx.x * 256 + threadIdx.x;
    const int  kg  = (int)(idx & 511);
    const long r   = idx >> 9;
    const int  n   = (int)(r & 2047);
    const int  l   = (int)(r >> 11);
    const int  k   = kg * 8;

    const float* s = W + (((size_t)l * XD + n) * KH + k);
    const float4 a = *(const float4*)s;
    const float4 b = *(const float4*)(s + 4);
    uint32_t hw[4], lw[4];
    split2h(a.x, a.y, hw[0], lw[0]);
    split2h(a.z, a.w, hw[1], lw[1]);
    split2h(b.x, b.y, hw[2], lw[2]);
    split2h(b.z, b.w, hw[3], lw[3]);

    const int nt = n >> 7, kb = k >> 9, c = (k >> 6) & 7;
    const int rw = n & 127, col = k & 63;
    size_t base = ((size_t)((l * 16 + nt) * 8 + kb) * 8 + c) * BCB
                + (size_t)rw * ROWB + col * 2;
    *(uint4*)(g_Wp + base)       = make_uint4(hw[0], hw[1], hw[2], hw[3]);
    *(uint4*)(g_Wp + base + BPL) = make_uint4(lw[0], lw[1], lw[2], lw[3]);
}

// ---------------------------------------------------------------------------
// Persistent kernel. SMEM: [A phase buffer 8*ACBA][B stage0][B stage1].
// 2-product fp16: acc += A*Bhi + A*Blo; epilogue rescales rows by 2^e.
// ---------------------------------------------------------------------------
__global__ void __launch_bounds__(256, 1)
rnn_persistent(const float* __restrict__ b_h,
               const int*   __restrict__ act_ids)
{
    extern __shared__ char dsm[];
    __shared__ __align__(8) unsigned long long s_mbB[2];
    __shared__ __align__(8) unsigned long long s_mbA[2];

    const int tid = threadIdx.x, wid = tid >> 5, lane = tid & 31;
    const int cta = blockIdx.x, nt = cta & 15, kb = cta >> 4;

    const uint32_t raw = s2u(dsm);
    const uint32_t A0u = (raw + 127) & ~127u;
    const uint32_t B0u = A0u + 8 * ACBA;
    const uint32_t mbB[2] = { s2u(&s_mbB[0]), s2u(&s_mbB[1]) };
    const uint32_t mbA[2] = { s2u(&s_mbA[0]), s2u(&s_mbA[1]) };

    if (tid == 0) {
        mbar_init(mbB[0], 1); mbar_init(mbB[1], 1);
        mbar_init(mbA[0], 1); mbar_init(mbA[1], 1);
        PROXY_FENCE();
    }
    __syncthreads();

    auto issueB = [&](long cg) {
        if (cg >= NCHUNK) return;
        const int s = (int)(cg & 1);
        const int p = (int)((cg >> 3) & 3);
        const int c = (int)(cg & 7);
        const unsigned char* src =
            g_Wp + ((size_t)((p * 16 + nt) * 8 + kb) * 8 + c) * BCB;
        mbar_expect(mbB[s], (uint32_t)BCB);
        bulk_g2s(B0u + s * BCB, src, (uint32_t)BCB, mbB[s]);
    };
    if (tid == 0) { issueB(0); issueB(1); }

    // fragment geometry
    const int g  = lane >> 2, i4 = lane & 3;
    const int wm = (wid >> 2) * 32;
    const int wn = (wid & 3) * 32;
    const int l15 = lane & 15, lk = lane >> 4;
    const uint32_t aoff0 = (uint32_t)((wm + l15) * ROWB + lk * 16);
    const uint32_t aoff1 = (uint32_t)((wm + 16 + l15) * ROWB + lk * 16);
    const int lr = lane & 7, ls8 = (lane >> 3) & 1;
    const uint32_t boff0 = (uint32_t)((wn + lk * 8 + lr) * ROWB + ls8 * 16);
    const uint32_t boff1 = (uint32_t)((wn + 16 + lk * 8 + lr) * ROWB + ls8 * 16);

    const int half = (kb & 3) >> 1;   // which 1024-col half the A slice is in

    int phb[2] = { 0, 0 };
    unsigned ls = 0;

    for (int pidx = 0; pidx < NPHASE; pidx++) {
        const int t = pidx >> 2, phn = pidx & 3;
        const int pa = pidx & 1;

        // phase sources / sinks
        const unsigned char *A1b, *A2b;
        const float* bias; const int* ids;
        float* dst32 = nullptr; long ldc = XD;
        unsigned char* dstb; float* saw;
        const float* sArr;
        const float* npr = nullptr; float* npw = nullptr; int zr = 0;
        if (phn == 0) {
            A1b = g_H0b + (size_t)t * 32 * ACBA;
            A2b = g_H4b + (size_t)(t ? t - 1 : 0) * 32 * ACBA;
            sArr = (kb < 4) ? g_saH0 + (size_t)t * 128
                            : g_saH4 + (size_t)(t ? t - 1 : 0) * 128;
            npr = g_np_bp[(t + 1) & 1]; zr = (t == 0);
            bias = b_h;        ids = act_ids + XD;
            dstb = g_h1b; saw = g_sa1;
        } else if (phn == 1) {
            A1b = g_h1b; A2b = g_h2b;
            sArr = (kb < 4) ? g_sa1 : g_sa2;
            npr = g_np_li[(t + 1) & 1]; zr = (t == 0);
            npw = g_np_li[t & 1];
            bias = b_h + XD;   ids = act_ids + 2*XD;
            dstb = g_h2b; saw = g_sa2;
        } else if (phn == 2) {
            A1b = g_h2b; A2b = g_h1b;
            sArr = (kb < 4) ? g_sa2 : g_sa1;
            bias = b_h + 2*XD; ids = act_ids + 3*XD;
            dstb = g_h3b; saw = g_sa3;
        } else {
            A1b = g_h3b; A2b = g_h2b;
            sArr = (kb < 4) ? g_sa3 : g_sa2;
            npw = g_np_bp[t & 1];
            bias = b_h + 3*XD; ids = act_ids + 4*XD;
            dstb = g_H4b + (size_t)t * 32 * ACBA;
            saw = g_saH4 + (size_t)t * 128;
            dst32 = g_H4 + (size_t)t * XD; ldc = (long)TSTEPS * XD;
        }

        const unsigned char* Asl = (kb < 4) ? A1b + (size_t)kb * 8 * ACBA
                                            : A2b + (size_t)(kb - 4) * 8 * ACBA;

        // Stage whole-phase A (chunk 0 first so compute starts early).
        if (tid == 0) {
            mbar_expect(mbA[0], (uint32_t)ACBA);
            bulk_g2s(A0u, Asl, (uint32_t)ACBA, mbA[0]);
            mbar_expect(mbA[1], (uint32_t)(7 * ACBA));
            bulk_g2s(A0u + ACBA, Asl + ACBA, (uint32_t)(7 * ACBA), mbA[1]);
        }

        float acc[2][4][4];
        #pragma unroll
        for (int mt = 0; mt < 2; mt++)
            #pragma unroll
            for (int n4 = 0; n4 < 4; n4++)
                #pragma unroll
                for (int j = 0; j < 4; j++) acc[mt][n4][j] = 0.f;

        const long cgb = (long)pidx * 8;
        #pragma unroll 1
        for (int c = 0; c < 8; c++) {
            const int s = c & 1;
            mbar_wait(mbB[s], (uint32_t)phb[s]); phb[s] ^= 1;
            if (c == 0) mbar_wait(mbA[0], (uint32_t)pa);
            if (c == 1) mbar_wait(mbA[1], (uint32_t)pa);

            const uint32_t bA = A0u + c * ACBA;
            const uint32_t bB = B0u + s * BCB;

            #pragma unroll
            for (int ks = 0; ks < 4; ks++) {
                const uint32_t kof = ks * 32;
                uint32_t ah[2][4], bhp[2][4], blp[2][4];
                ldsm4(ah[0], bA + aoff0 + kof);
                ldsm4(ah[1], bA + aoff1 + kof);
                ldsm4(bhp[0], bB + boff0 + kof);
                ldsm4(bhp[1], bB + boff1 + kof);
                ldsm4(blp[0], bB + BPL + boff0 + kof);
                ldsm4(blp[1], bB + BPL + boff1 + kof);
                #pragma unroll
                for (int mt = 0; mt < 2; mt++)
                    #pragma unroll
                    for (int P = 0; P < 2; P++) {
                        MMA(acc[mt][2*P],   ah[mt], bhp[P] + 0);
                        MMA(acc[mt][2*P],   ah[mt], blp[P] + 0);
                        MMA(acc[mt][2*P+1], ah[mt], bhp[P] + 2);
                        MMA(acc[mt][2*P+1], ah[mt], blp[P] + 2);
                    }
            }
            __syncthreads();
            if (tid == 0) issueB(cgb + c + 2);   // crosses into next phase
        }

        // epilogue: rescale rows by the source's 2^e and write partials
        {
            float* P = g_part + (size_t)kb * BATCH * XD;
            #pragma unroll
            for (int mt = 0; mt < 2; mt++) {
                const int m = wm + mt * 16 + g;
                const float s0 = sArr[2 * m + half];
                const float s1 = sArr[2 * (m + 8) + half];
                #pragma unroll
                for (int n4 = 0; n4 < 4; n4++) {
                    const int col = nt * 128 + wn + n4 * 8 + i4 * 2;
                    *(float2*)&P[(size_t)m * XD + col] =
                        make_float2(acc[mt][n4][0] * s0, acc[mt][n4][1] * s0);
                    *(float2*)&P[(size_t)(m + 8) * XD + col] =
                        make_float2(acc[mt][n4][2] * s1, acc[mt][n4][3] * s1);
                }
            }
        }

        gbar(ls);
        reduce_phase(bias, ids, dst32, ldc, dstb, saw, npr, zr, npw, cta);
        gbar(ls);
    }
}

// ---------------------------------------------------------------------------
// Parallel fp32 SIMT GEMM with fused bias+activation (edge GEMMs).
// If Cb != null, writes fp16 chunk layout (H0: values ~1e2, scale 1 safe).
// ---------------------------------------------------------------------------
__global__ void __launch_bounds__(256, 1)
gemm_big(const float* __restrict__ A, int lda,
         const float* __restrict__ W, int K,
         const float* __restrict__ bias,
         const int*   __restrict__ ids,
         float* __restrict__ C, int ldc,
         unsigned char* __restrict__ Cb)
{
    __shared__ float As[32][64];
    __shared__ float Ws[32][128];

    const int t  = threadIdx.x;
    const int n0 = blockIdx.x * 128;
    const int m0 = blockIdx.y * 64;

    const int am  = t & 63;
    const int akq = t >> 6;
    const int wn  = t & 127;
    const int wkq = t >> 7;

    const float* Aptr = A + (size_t)(m0 + am) * lda + akq * 8;
    const float* Wptr = W + (size_t)(n0 + wn) * K + wkq * 16;

    float4 pa0 = *(const float4*)(Aptr + 0);
    float4 pa1 = *(const float4*)(Aptr + 4);
    float4 pw0 = *(const float4*)(Wptr + 0);
    float4 pw1 = *(const float4*)(Wptr + 4);
    float4 pw2 = *(const float4*)(Wptr + 8);
    float4 pw3 = *(const float4*)(Wptr + 12);

    const int tx = t & 31;
    const int ty = t >> 5;

    float c[8][4];
    #pragma unroll
    for (int i = 0; i < 8; i++)
        #pragma unroll
        for (int j = 0; j < 4; j++) c[i][j] = 0.f;

    const int NC = K / 32;
    #pragma unroll 1
    for (int ch = 0; ch < NC; ch++) {
        __syncthreads();
        As[akq*8+0][am] = pa0.x; As[akq*8+1][am] = pa0.y;
        As[akq*8+2][am] = pa0.z; As[akq*8+3][am] = pa0.w;
        As[akq*8+4][am] = pa1.x; As[akq*8+5][am] = pa1.y;
        As[akq*8+6][am] = pa1.z; As[akq*8+7][am] = pa1.w;
        Ws[wkq*16+ 0][wn] = pw0.x; Ws[wkq*16+ 1][wn] = pw0.y;
        Ws[wkq*16+ 2][wn] = pw0.z; Ws[wkq*16+ 3][wn] = pw0.w;
        Ws[wkq*16+ 4][wn] = pw1.x; Ws[wkq*16+ 5][wn] = pw1.y;
        Ws[wkq*16+ 6][wn] = pw1.z; Ws[wkq*16+ 7][wn] = pw1.w;
        Ws[wkq*16+ 8][wn] = pw2.x; Ws[wkq*16+ 9][wn] = pw2.y;
        Ws[wkq*16+10][wn] = pw2.z; Ws[wkq*16+11][wn] = pw2.w;
        Ws[wkq*16+12][wn] = pw3.x; Ws[wkq*16+13][wn] = pw3.y;
        Ws[wkq*16+14][wn] = pw3.z; Ws[wkq*16+15][wn] = pw3.w;
        __syncthreads();

        if (ch + 1 < NC) {
            Aptr += 32; Wptr += 32;
            pa0 = *(const float4*)(Aptr + 0);
            pa1 = *(const float4*)(Aptr + 4);
            pw0 = *(const float4*)(Wptr + 0);
            pw1 = *(const float4*)(Wptr + 4);
            pw2 = *(const float4*)(Wptr + 8);
            pw3 = *(const float4*)(Wptr + 12);
        }

        #pragma unroll
        for (int kk = 0; kk < 32; kk++) {
            const float4 a0 = *(const float4*)&As[kk][ty*8];
            const float4 a1 = *(const float4*)&As[kk][ty*8+4];
            const float4 w  = *(const float4*)&Ws[kk][tx*4];
            const float av[8] = {a0.x,a0.y,a0.z,a0.w,a1.x,a1.y,a1.z,a1.w};
            const float wv[4] = {w.x,w.y,w.z,w.w};
            #pragma unroll
            for (int i = 0; i < 8; i++)
                #pragma unroll
                for (int j = 0; j < 4; j++)
                    c[i][j] = fmaf(av[i], wv[j], c[i][j]);
        }
    }

    #pragma unroll
    for (int i = 0; i < 8; i++) {
        const int m = m0 + ty * 8 + i;
        const int n = n0 + tx * 4;
        float4 o;
        o.x = act_f(c[i][0] + bias[n+0], ids[n+0]);
        o.y = act_f(c[i][1] + bias[n+1], ids[n+1]);
        o.z = act_f(c[i][2] + bias[n+2], ids[n+2]);
        o.w = act_f(c[i][3] + bias[n+3], ids[n+3]);
        if (Cb) {
            const int tt = m & 127, bb = m >> 7;
            const int gch = n >> 6, col = n & 63;
            unsigned char* base = Cb + ((size_t)tt * 32 + gch) * ACBA
                                + bb * ROWB + col * 2;
            *(uint2*)base = make_uint2(packh(o.x, o.y), packh(o.z, o.w));
        } else {
            *(float4*)&C[(size_t)m * ldc + n] = o;
        }
    }
}

// Zero barrier state + carry buffers read (scaled by 0) at t=0; init scales.
__global__ void init_state()
{
    const int i = blockIdx.x * blockDim.x + threadIdx.x;
    if (i == 0) { g_cnt = 0u; g_sense = 0u; }
    const uint4 z = make_uint4(0, 0, 0, 0);
    if (i < 18432) {                               // 32*ACBA/16
        *(uint4*)(g_h2b + (size_t)i * 16) = z;
        *(uint4*)(g_H4b + (size_t)i * 16) = z;     // slice t=0
    }
    if (i < 16384) g_saH0[i] = 1.f;                // H0: fixed scale 1
    if (i < 128) { g_saH4[i] = 1.f; g_sa2[i] = 1.f; }
}

// ---------------------------------------------------------------------------
extern "C" void kernel_launch(void* const* d_in, const int* in_sizes, int n_in,
                              void* d_out, int out_size)
{
    const float* x        = (const float*)d_in[0];  // [64,128,512]
    const float* W_in     = (const float*)d_in[1];  // [2048,512]
    const float* b_in     = (const float*)d_in[2];  // [2048]
    const float* W_h      = (const float*)d_in[3];  // [4,2048,4096]
    const float* b_h      = (const float*)d_in[4];  // [4,2048]
    const float* W_out    = (const float*)d_in[5];  // [256,2048]
    const float* b_out    = (const float*)d_in[6];  // [256]
    const int*   act_ids  = (const int*)d_in[7];    // [5,2048]
    const int*   oact_ids = (const int*)d_in[8];    // [256]
    float*       out      = (float*)d_out;          // [64,128,256]

    float *H4;
    unsigned char *H0b;
    cudaGetSymbolAddress((void**)&H4, g_H4);
    cudaGetSymbolAddress((void**)&H0b, g_H0b);

    const int smem = 8 * ACBA + 2 * BCB + 128;      // 147,584
    cudaFuncSetAttribute(rnn_persistent,
                         cudaFuncAttributeMaxDynamicSharedMemorySize, smem);

    init_state<<<288, 256>>>();
    prep_w<<<16384, 256>>>(W_h);

    // H0 = act0(x @ W_in^T + b_in), written straight into fp16 chunk layout.
    gemm_big<<<dim3(XD/128, BT/64), 256>>>(x, INDIM, W_in, INDIM,
                                           b_in, act_ids, nullptr, 0, H0b);

    // Entire recurrent loop: persistent fp16 2-product HMMA kernel.
    rnn_persistent<<<NCTA, 256, smem>>>(b_h, act_ids);

    // y = act_out(H4 @ W_out^T + b_out)
    gemm_big<<<dim3(OUTDIM/128, BT/64), 256>>>(H4, XD, W_out, XD,
                                               b_out, oact_ids, out, OUTDIM,
                                               nullptr);
}